// round 4
// baseline (speedup 1.0000x reference)
#include <cuda_runtime.h>
#include <cuda_bf16.h>
#include <math.h>

// ---------------- problem constants ----------------
#define NB   8
#define NV_  100
#define LQ   128
#define NKG_ 923
#define NT_  1024
#define DV_  2048
#define DK_  300
#define DH_  1024
#define NH_  8
#define DHD_ 128
#define NL_  3

// ---------------- device scratch (static globals: allowed) ----------------
__device__ float    g_x [NB*NT_*DH_];   // node features [B,NT,DH]
__device__ float    g_h [NB*NT_*DH_];   // per-layer h = xW+b
__device__ float    g_y [NB*NT_*DH_];   // staging (proj outputs / GAT agg out)
__device__ float    g_s  [NB*NT_*NH_];  // [b, i, h]
__device__ float    g_p1 [NB*NT_*NH_];  // exp(s)/denom      [b, i, h]
__device__ float    g_p2 [NB*NT_*NH_];  // exp(0.2 s)/denom  [b, i, h]
// transposed [b, h, j] copies for coalesced j-scans:
__device__ float    g_tT [NB*NH_*NT_];  // t
__device__ float    g_e1T[NB*NH_*NT_];  // exp(t)
__device__ float    g_e2T[NB*NH_*NT_];  // exp(0.2 t)
__device__ unsigned g_mb [NB*NT_*(NT_/32)]; // adjacency bitmask
__device__ float    g_pool[NB*DH_];
__device__ float    g_sc  [NB*NT_];
__device__ float    g_gv  [NB*DH_];
__device__ float    g_hm  [NB*DH_];

// ---------------- generic fp32 SGEMM: C[M,N] = A[M,K]*B[K,N] + bias ----------------
// 128x128 tile, BK=8, 256 threads, 8x8 per thread.
__global__ void __launch_bounds__(256) sgemm_kernel(
    const float* __restrict__ A, const float* __restrict__ Bm,
    const float* __restrict__ bias, float* __restrict__ C,
    int M, int N, int K)
{
    __shared__ float As[8][132];   // padded: staging writes stride 132 -> conflict-free
    __shared__ float Bs[8][128];
    int tid = threadIdx.x;
    int tx = tid & 15, ty = tid >> 4;
    int rowBase = blockIdx.y * 128;
    int colBase = blockIdx.x * 128;
    float acc[8][8];
    #pragma unroll
    for (int m = 0; m < 8; m++)
        #pragma unroll
        for (int n = 0; n < 8; n++) acc[m][n] = 0.f;

    for (int k0 = 0; k0 < K; k0 += 8) {
        #pragma unroll
        for (int i = 0; i < 4; i++) {
            int lin = tid + i * 256;
            int r = lin >> 3, c = lin & 7;
            int gr = rowBase + r, gc = k0 + c;
            As[c][r] = (gr < M && gc < K) ? A[(size_t)gr * K + gc] : 0.f;
        }
        #pragma unroll
        for (int i = 0; i < 4; i++) {
            int lin = tid + i * 256;
            int r = lin >> 7, c = lin & 127;
            int gr = k0 + r, gc = colBase + c;
            Bs[r][c] = (gr < K && gc < N) ? Bm[(size_t)gr * N + gc] : 0.f;
        }
        __syncthreads();
        #pragma unroll
        for (int k = 0; k < 8; k++) {
            float ra[8], rb[8];
            #pragma unroll
            for (int m = 0; m < 8; m++) ra[m] = As[k][ty * 8 + m];
            #pragma unroll
            for (int n = 0; n < 8; n++) rb[n] = Bs[k][tx * 8 + n];
            #pragma unroll
            for (int m = 0; m < 8; m++)
                #pragma unroll
                for (int n = 0; n < 8; n++) acc[m][n] += ra[m] * rb[n];
        }
        __syncthreads();
    }
    #pragma unroll
    for (int m = 0; m < 8; m++) {
        int gr = rowBase + ty * 8 + m;
        if (gr >= M) continue;
        #pragma unroll
        for (int n = 0; n < 8; n++) {
            int gc = colBase + tx * 8 + n;
            if (gc < N) C[(size_t)gr * N + gc] = acc[m][n] + (bias ? bias[gc] : 0.f);
        }
    }
}

// ---------------- LayerNorm over DH=1024 with flexible row mapping ----------------
__global__ void __launch_bounds__(256) ln_kernel(
    const float* __restrict__ src,
    const float* __restrict__ gamma, const float* __restrict__ beta,
    int npb, int node_off, int residual)
{
    int r = blockIdx.x;
    int bb = r / npb, n = r % npb;
    size_t srow = (size_t)r * DH_;
    size_t drow = ((size_t)bb * NT_ + node_off + n) * DH_;
    int t = threadIdx.x;
    float v[4];
    #pragma unroll
    for (int i = 0; i < 4; i++) {
        int d = t + i * 256;
        float val = src[srow + d];
        if (residual) val += g_x[drow + d];
        v[i] = val;
    }
    float s  = v[0] + v[1] + v[2] + v[3];
    float sq = v[0]*v[0] + v[1]*v[1] + v[2]*v[2] + v[3]*v[3];
    __shared__ float shs[8], shq[8], fin[2];
    #pragma unroll
    for (int o = 16; o; o >>= 1) {
        s  += __shfl_xor_sync(0xffffffffu, s,  o);
        sq += __shfl_xor_sync(0xffffffffu, sq, o);
    }
    if ((t & 31) == 0) { shs[t >> 5] = s; shq[t >> 5] = sq; }
    __syncthreads();
    if (t == 0) {
        float a = 0.f, b2 = 0.f;
        #pragma unroll
        for (int i = 0; i < 8; i++) { a += shs[i]; b2 += shq[i]; }
        float mean = a * (1.f / DH_);
        float var  = b2 * (1.f / DH_) - mean * mean;
        fin[0] = mean;
        fin[1] = rsqrtf(var + 1e-5f);
    }
    __syncthreads();
    float mean = fin[0], inv = fin[1];
    #pragma unroll
    for (int i = 0; i < 4; i++) {
        int d = t + i * 256;
        g_x[drow + d] = (v[i] - mean) * inv * gamma[d] + beta[d];
    }
}

// ---------------- text masked mean-pool ----------------
__global__ void text_pool_kernel(const int* __restrict__ ids, const int* __restrict__ am,
                                 const float* __restrict__ temb)
{
    int b = blockIdx.y;
    int d = blockIdx.x * 256 + threadIdx.x;
    float sum = 0.f, cnt = 0.f;
    for (int l = 0; l < LQ; l++) {
        float mv = (float)am[b * LQ + l];
        sum += mv * temb[(size_t)ids[b * LQ + l] * DH_ + d];
        cnt += mv;
    }
    g_pool[b * DH_ + d] = sum / fmaxf(cnt, 1.f);
}

// ---------------- add type embeddings ----------------
__global__ void type_add_kernel(const int* __restrict__ types, const float* __restrict__ temb)
{
    size_t idx = (size_t)blockIdx.x * 256 + threadIdx.x;  // B*NT*DH
    int node = (int)(idx >> 10);
    int d = (int)(idx & (DH_ - 1));
    g_x[idx] += temb[types[node] * DH_ + d];
}

// ---------------- adjacency -> bitmask ----------------
__global__ void mask_kernel(const int* __restrict__ adj)
{
    int w = blockIdx.x * 256 + threadIdx.x;     // B*NT*32 words
    const int* row = adj + (size_t)w * 32;
    unsigned m = 0u;
    #pragma unroll
    for (int i = 0; i < 32; i++) m |= (row[i] > 0) ? (1u << i) : 0u;
    g_mb[w] = m;
}

// ---------------- per-node s,t and exp factors ----------------
// Writes s (interleaved [b,i,h]) and transposed t/exp factors ([b,h,j]).
__global__ void st_kernel(const float* __restrict__ asrc, const float* __restrict__ adst)
{
    int bn = blockIdx.x;                         // b*NT+n
    int b = bn >> 10, n = bn & (NT_ - 1);
    int w = threadIdx.x >> 5, lane = threadIdx.x & 31;
    const float* hr = g_h + ((size_t)bn << 10) + (w << 7);
    float sv = 0.f, tv = 0.f;
    #pragma unroll
    for (int i = 0; i < 4; i++) {
        float hv = hr[lane + i * 32];
        sv += hv * asrc[w * DHD_ + lane + i * 32];
        tv += hv * adst[w * DHD_ + lane + i * 32];
    }
    #pragma unroll
    for (int o = 16; o; o >>= 1) {
        sv += __shfl_xor_sync(0xffffffffu, sv, o);
        tv += __shfl_xor_sync(0xffffffffu, tv, o);
    }
    if (lane == 0) {
        g_s[bn * NH_ + w] = sv;
        int idxT = ((b * NH_ + w) << 10) + n;
        g_tT [idxT] = tv;
        g_e1T[idxT] = expf(tv);
        g_e2T[idxT] = expf(0.2f * tv);
    }
}

// ---------------- softmax row stats (no per-element exp!) ----------------
// exp(lrelu(s+t)) = (s+t>=0) ? exp(s)exp(t) : exp(0.2s)exp(0.2t)
// denom_i = exp(s_i)*S1 + exp(0.2 s_i)*S2, P1 = exp(s)/denom, P2 = exp(0.2s)/denom.
__global__ void stats_kernel()
{
    int bi = blockIdx.x;                 // b*NT + i
    int b = bi >> 10;
    int hd = threadIdx.x >> 5, lane = threadIdx.x & 31;
    float si = g_s[bi * NH_ + hd];
    const unsigned* mrow = g_mb + (size_t)bi * 32;
    const float* tT  = g_tT  + ((b * NH_ + hd) << 10);
    const float* e1T = g_e1T + ((b * NH_ + hd) << 10);
    const float* e2T = g_e2T + ((b * NH_ + hd) << 10);
    float S1 = 0.f, S2 = 0.f;
    for (int it = 0; it < 32; it++) {
        unsigned wd = mrow[it];
        if ((wd >> lane) & 1u) {
            int j = it * 32 + lane;
            if (si + tT[j] >= 0.f) S1 += e1T[j]; else S2 += e2T[j];
        }
    }
    #pragma unroll
    for (int o = 16; o; o >>= 1) {
        S1 += __shfl_xor_sync(0xffffffffu, S1, o);
        S2 += __shfl_xor_sync(0xffffffffu, S2, o);
    }
    if (lane == 0) {
        float e1 = expf(si), e2 = expf(0.2f * si);
        float inv = 1.f / (e1 * S1 + e2 * S2);
        g_p1[bi * NH_ + hd] = e1 * inv;
        g_p2[bi * NH_ + hd] = e2 * inv;
    }
}

// ---------------- GAT aggregation: per (b,head) generated-A GEMM ----------------
// out[i,d] = sum_j w_ij * h[j, head, d], w generated on the fly in the A tile.
// BM=64, BN=128(full head dim), BK=32, 256 threads, 4x8 per thread.
__global__ void __launch_bounds__(256) gat_agg_kernel()
{
    int b = blockIdx.z, hd = blockIdx.y;
    int rowBase = blockIdx.x * 64;
    int tid = threadIdx.x;
    int tx = tid & 15, ty = tid >> 4;

    __shared__ __align__(16) float As[32][68];   // [k(j)][m(i)] padded
    __shared__ float4 Bs[32][32];                // [k(j)][d/4]

    int m  = tid & 63;
    int jb = tid >> 6;                           // this thread's base jj in {0..3}
    int bi_m = (b << 10) + rowBase + m;
    float smv = g_s [bi_m * NH_ + hd];
    float pr1 = g_p1[bi_m * NH_ + hd];
    float pr2 = g_p2[bi_m * NH_ + hd];
    const unsigned* mrow = g_mb + (size_t)bi_m * 32;
    const float* tT  = g_tT  + ((b * NH_ + hd) << 10);
    const float* e1T = g_e1T + ((b * NH_ + hd) << 10);
    const float* e2T = g_e2T + ((b * NH_ + hd) << 10);

    float acc[4][8];
    #pragma unroll
    for (int a = 0; a < 4; a++)
        #pragma unroll
        for (int n = 0; n < 8; n++) acc[a][n] = 0.f;

    for (int k0 = 0; k0 < NT_; k0 += 32) {
        #pragma unroll
        for (int i = 0; i < 4; i++) {
            int lin = tid + i * 256;             // 1024 float4s
            int r = lin >> 5, c4 = lin & 31;
            const float4* src = (const float4*)(g_h + (((size_t)((b << 10) + k0 + r)) << 10) + (hd << 7));
            Bs[r][c4] = src[c4];
        }
        unsigned mword = mrow[k0 >> 5];
        #pragma unroll
        for (int i = 0; i < 8; i++) {
            int jj = jb + i * 4;
            float wv = 0.f;
            if ((mword >> jj) & 1u) {
                int j = k0 + jj;
                wv = (smv + tT[j] >= 0.f) ? pr1 * e1T[j] : pr2 * e2T[j];
            }
            As[jj][m] = wv;
        }
        __syncthreads();
        #pragma unroll
        for (int k = 0; k < 32; k++) {
            float4 ra = *(const float4*)&As[k][ty << 2];
            float4 b0 = Bs[k][tx << 1];
            float4 b1 = Bs[k][(tx << 1) + 1];
            float ram[4] = {ra.x, ra.y, ra.z, ra.w};
            float rbn[8] = {b0.x, b0.y, b0.z, b0.w, b1.x, b1.y, b1.z, b1.w};
            #pragma unroll
            for (int a = 0; a < 4; a++)
                #pragma unroll
                for (int n = 0; n < 8; n++) acc[a][n] += ram[a] * rbn[n];
        }
        __syncthreads();
    }
    #pragma unroll
    for (int a = 0; a < 4; a++) {
        int gi = rowBase + (ty << 2) + a;
        float* dst = g_y + (((size_t)((b << 10) + gi)) << 10) + (hd << 7) + (tx << 3);
        float4* d4 = (float4*)dst;
        d4[0] = make_float4(acc[a][0], acc[a][1], acc[a][2], acc[a][3]);
        d4[1] = make_float4(acc[a][4], acc[a][5], acc[a][6], acc[a][7]);
    }
}

// ---------------- readout score per node ----------------
__global__ void score_kernel(const float* __restrict__ rw, const float* __restrict__ rb)
{
    int gwarp = (blockIdx.x * 256 + threadIdx.x) >> 5;   // b*NT+n
    int lane = threadIdx.x & 31;
    const float* xr = g_x + ((size_t)gwarp << 10);
    float sv = 0.f;
    #pragma unroll
    for (int i = 0; i < 32; i++) sv += xr[lane + i * 32] * rw[lane + i * 32];
    #pragma unroll
    for (int o = 16; o; o >>= 1) sv += __shfl_xor_sync(0xffffffffu, sv, o);
    if (lane == 0) g_sc[gwarp] = sv + rb[0];
}

// ---------------- softmax over nodes + weighted pool ----------------
__global__ void readout_pool_kernel()
{
    int b = blockIdx.y;
    int d = blockIdx.x * 256 + threadIdx.x;
    int tid = threadIdx.x;
    __shared__ float p[NT_];
    __shared__ float red[9];
    float mx = -1e30f;
    #pragma unroll
    for (int i = 0; i < 4; i++) mx = fmaxf(mx, g_sc[b * NT_ + tid + i * 256]);
    #pragma unroll
    for (int o = 16; o; o >>= 1) mx = fmaxf(mx, __shfl_xor_sync(0xffffffffu, mx, o));
    if ((tid & 31) == 0) red[tid >> 5] = mx;
    __syncthreads();
    if (tid == 0) {
        float mm = red[0];
        #pragma unroll
        for (int i = 1; i < 8; i++) mm = fmaxf(mm, red[i]);
        red[8] = mm;
    }
    __syncthreads();
    mx = red[8];
    float sum = 0.f;
    #pragma unroll
    for (int i = 0; i < 4; i++) {
        int n = tid + i * 256;
        float e = expf(g_sc[b * NT_ + n] - mx);
        p[n] = e; sum += e;
    }
    #pragma unroll
    for (int o = 16; o; o >>= 1) sum += __shfl_xor_sync(0xffffffffu, sum, o);
    __syncthreads();
    if ((tid & 31) == 0) red[tid >> 5] = sum;
    __syncthreads();
    if (tid == 0) {
        float ss2 = 0.f;
        #pragma unroll
        for (int i = 0; i < 8; i++) ss2 += red[i];
        red[8] = 1.f / ss2;
    }
    __syncthreads();
    float inv = red[8];
    float acc = 0.f;
    for (int n = 0; n < NT_; n++)
        acc += p[n] * g_x[(((size_t)(b << 10)) + n) * DH_ + d];
    g_gv[b * DH_ + d] = acc * inv;
}

// ---------------- candidate scorer ----------------
__global__ void cs1_kernel(const float* __restrict__ W1, const float* __restrict__ b1)
{
    int b = blockIdx.y;
    int d = blockIdx.x * 256 + threadIdx.x;
    float sv = 0.f;
    for (int k = 0; k < DH_; k++) sv += g_gv[b * DH_ + k] * W1[(size_t)k * DH_ + d];
    sv += b1[d];
    float u = 0.7978845608028654f * (sv + 0.044715f * sv * sv * sv);
    g_hm[b * DH_ + d] = 0.5f * sv * (1.f + tanhf(u));
}

__global__ void cs2_kernel(const float* __restrict__ W2, const float* __restrict__ b2,
                           float* __restrict__ out)
{
    int b = blockIdx.x;
    int tid = threadIdx.x;
    float sv = 0.f;
    for (int i = tid; i < DH_; i += 256) sv += g_hm[b * DH_ + i] * W2[i];
    #pragma unroll
    for (int o = 16; o; o >>= 1) sv += __shfl_xor_sync(0xffffffffu, sv, o);
    __shared__ float red[8];
    if ((tid & 31) == 0) red[tid >> 5] = sv;
    __syncthreads();
    if (tid == 0) {
        float tot = 0.f;
        #pragma unroll
        for (int i = 0; i < 8; i++) tot += red[i];
        out[b] = tot + b2[0];
    }
}

extern "C" void kernel_launch(void* const* d_in, const int* in_sizes, int n_in,
                              void* d_out, int out_size)
{
    const float* visf   = (const float*)d_in[0];
    const int*   qids   = (const int*)  d_in[1];
    const int*   qam    = (const int*)  d_in[2];
    const float* kgf    = (const float*)d_in[3];
    const int*   adj    = (const int*)  d_in[4];
    const int*   types  = (const int*)  d_in[5];
    const float* vis_W  = (const float*)d_in[6];
    const float* vis_b  = (const float*)d_in[7];
    const float* vis_lg = (const float*)d_in[8];
    const float* vis_lb = (const float*)d_in[9];
    const float* tok    = (const float*)d_in[10];
    const float* q_W    = (const float*)d_in[11];
    const float* q_b    = (const float*)d_in[12];
    const float* q_lg   = (const float*)d_in[13];
    const float* q_lb   = (const float*)d_in[14];
    const float* kg_W   = (const float*)d_in[15];
    const float* kg_b   = (const float*)d_in[16];
    const float* kg_lg  = (const float*)d_in[17];
    const float* kg_lb  = (const float*)d_in[18];
    const float* temb   = (const float*)d_in[19];
    const float* gat_W  = (const float*)d_in[20];
    const float* gat_b  = (const float*)d_in[21];
    const float* a_src  = (const float*)d_in[22];
    const float* a_dst  = (const float*)d_in[23];
    const float* gat_lg = (const float*)d_in[24];
    const float* gat_lb = (const float*)d_in[25];
    const float* rW     = (const float*)d_in[26];
    const float* rb     = (const float*)d_in[27];
    const float* csW1   = (const float*)d_in[28];
    const float* csb1   = (const float*)d_in[29];
    const float* csW2   = (const float*)d_in[30];
    const float* csb2   = (const float*)d_in[31];
    float* out = (float*)d_out;

    float *x, *h, *y, *pool;
    cudaGetSymbolAddress((void**)&x,    g_x);
    cudaGetSymbolAddress((void**)&h,    g_h);
    cudaGetSymbolAddress((void**)&y,    g_y);
    cudaGetSymbolAddress((void**)&pool, g_pool);

    // 1. visual projection + LN  -> x[:, 0:100]
    sgemm_kernel<<<dim3(8, (NB*NV_ + 127) / 128), 256>>>(visf, vis_W, vis_b, y, NB*NV_, DH_, DV_);
    ln_kernel<<<NB*NV_, 256>>>(y, vis_lg, vis_lb, NV_, 0, 0);

    // 2. text pool + proj + LN   -> x[:, 100]
    text_pool_kernel<<<dim3(4, NB), 256>>>(qids, qam, tok);
    sgemm_kernel<<<dim3(8, 1), 256>>>(pool, q_W, q_b, y, NB, DH_, DH_);
    ln_kernel<<<NB, 256>>>(y, q_lg, q_lb, 1, NV_, 0);

    // 3. KG projection + LN      -> x[:, 101:1024]
    sgemm_kernel<<<dim3(8, (NB*NKG_ + 127) / 128), 256>>>(kgf, kg_W, kg_b, y, NB*NKG_, DH_, DK_);
    ln_kernel<<<NB*NKG_, 256>>>(y, kg_lg, kg_lb, NKG_, NV_ + 1, 0);

    // 4. type embeddings, adjacency bitmask
    type_add_kernel<<<(NB*NT_*DH_) / 256, 256>>>(types, temb);
    mask_kernel<<<(NB*NT_*32) / 256, 256>>>(adj);

    // 5. GAT layers
    for (int l = 0; l < NL_; l++) {
        sgemm_kernel<<<dim3(8, 64), 256>>>(x, gat_W + (size_t)l*DH_*DH_, gat_b + l*DH_, h,
                                           NB*NT_, DH_, DH_);
        st_kernel<<<NB*NT_, 256>>>(a_src + l*NH_*DHD_, a_dst + l*NH_*DHD_);
        stats_kernel<<<NB*NT_, 256>>>();
        gat_agg_kernel<<<dim3(16, NH_, NB), 256>>>();
        ln_kernel<<<NB*NT_, 256>>>(y, gat_lg + l*DH_, gat_lb + l*DH_, NT_, 0, 1);
    }

    // 6. readout + scorer
    score_kernel<<<(NB*NT_*32) / 256, 256>>>(rW, rb);
    readout_pool_kernel<<<dim3(4, NB), 256>>>();
    cs1_kernel<<<dim3(4, NB), 256>>>(csW1, csb1);
    cs2_kernel<<<NB, 256>>>(csW2, csb2, out);
}

// round 8
// speedup vs baseline: 1.0135x; 1.0135x over previous
#include <cuda_runtime.h>
#include <cuda_bf16.h>
#include <math.h>

// ---------------- problem constants ----------------
#define NB   8
#define NV_  100
#define LQ   128
#define NKG_ 923
#define NT_  1024
#define DV_  2048
#define DK_  300
#define DH_  1024
#define NH_  8
#define DHD_ 128
#define NL_  3

typedef unsigned long long u64;

// packed f32x2 helpers (Blackwell): each half is an IEEE fma -> bit-exact vs scalar
__device__ __forceinline__ u64 pack2(float lo, float hi) {
    u64 r; asm("mov.b64 %0, {%1, %2};" : "=l"(r) : "f"(lo), "f"(hi)); return r;
}
__device__ __forceinline__ float2 unpack2(u64 v) {
    float2 f; asm("mov.b64 {%0, %1}, %2;" : "=f"(f.x), "=f"(f.y) : "l"(v)); return f;
}
__device__ __forceinline__ u64 ffma2(u64 a, u64 b, u64 c) {
    u64 d; asm("fma.rn.f32x2 %0, %1, %2, %3;" : "=l"(d) : "l"(a), "l"(b), "l"(c)); return d;
}

// ---------------- device scratch ----------------
__device__ float    g_x [NB*NT_*DH_];
__device__ float    g_h [NB*NT_*DH_];
__device__ float    g_y [NB*NT_*DH_];
__device__ float    g_s  [NB*NT_*NH_];
__device__ float    g_p1 [NB*NT_*NH_];
__device__ float    g_p2 [NB*NT_*NH_];
__device__ float    g_tT [NB*NH_*NT_];
__device__ float    g_e1T[NB*NH_*NT_];
__device__ float    g_e2T[NB*NH_*NT_];
__device__ unsigned g_mb [NB*NT_*(NT_/32)];
__device__ float    g_pool[NB*DH_];
__device__ float    g_sc  [NB*NT_];
__device__ float    g_gv  [NB*DH_];
__device__ float    g_hm  [NB*DH_];

// ---------------- SGEMM: 128x128 tile, BK=8, double-buffered, FFMA2 ----------------
__global__ void __launch_bounds__(256) sgemm_kernel(
    const float* __restrict__ A, const float* __restrict__ Bm,
    const float* __restrict__ bias, float* __restrict__ C,
    int M, int N, int K)
{
    __shared__ __align__(16) float As[2][8][132];
    __shared__ __align__(16) float Bs[2][8][128];
    int tid = threadIdx.x;
    int tx = tid & 15, ty = tid >> 4;
    int rowBase = blockIdx.y * 128;
    int colBase = blockIdx.x * 128;

    // acc[mp][n]: row pair (ty*8+2mp, +1), col (tx*8+n)
    u64 acc[4][8];
    #pragma unroll
    for (int mp = 0; mp < 4; mp++)
        #pragma unroll
        for (int n = 0; n < 8; n++) acc[mp][n] = pack2(0.f, 0.f);

    float sa[4], sb[4];
    int nk = (K + 7) >> 3;

    // prefetch tile 0
    #pragma unroll
    for (int i = 0; i < 4; i++) {
        int lin = tid + i * 256;
        int r = lin >> 3, c = lin & 7;
        int gr = rowBase + r, gc = c;
        sa[i] = (gr < M && gc < K) ? A[(size_t)gr * K + gc] : 0.f;
    }
    #pragma unroll
    for (int i = 0; i < 4; i++) {
        int lin = tid + i * 256;
        int r = lin >> 7, c = lin & 127;
        int gr = r, gc = colBase + c;
        sb[i] = (gr < K && gc < N) ? Bm[(size_t)gr * N + gc] : 0.f;
    }
    #pragma unroll
    for (int i = 0; i < 4; i++) {
        int lin = tid + i * 256;
        As[0][lin & 7][lin >> 3] = sa[i];
        Bs[0][lin >> 7][lin & 127] = sb[i];
    }
    __syncthreads();

    int buf = 0;
    for (int it = 1; it <= nk; it++) {
        if (it < nk) {
            int k0 = it << 3;
            #pragma unroll
            for (int i = 0; i < 4; i++) {
                int lin = tid + i * 256;
                int r = lin >> 3, c = lin & 7;
                int gr = rowBase + r, gc = k0 + c;
                sa[i] = (gr < M && gc < K) ? A[(size_t)gr * K + gc] : 0.f;
            }
            #pragma unroll
            for (int i = 0; i < 4; i++) {
                int lin = tid + i * 256;
                int r = lin >> 7, c = lin & 127;
                int gr = k0 + r, gc = colBase + c;
                sb[i] = (gr < K && gc < N) ? Bm[(size_t)gr * N + gc] : 0.f;
            }
        }
        // compute current buffer
        #pragma unroll
        for (int k = 0; k < 8; k++) {
            u64 ap[4];
            #pragma unroll
            for (int mp = 0; mp < 4; mp++)
                ap[mp] = *(const u64*)&As[buf][k][ty * 8 + 2 * mp];
            float4 b0 = *(const float4*)&Bs[buf][k][tx * 8];
            float4 b1 = *(const float4*)&Bs[buf][k][tx * 8 + 4];
            u64 bp[8] = { pack2(b0.x, b0.x), pack2(b0.y, b0.y),
                          pack2(b0.z, b0.z), pack2(b0.w, b0.w),
                          pack2(b1.x, b1.x), pack2(b1.y, b1.y),
                          pack2(b1.z, b1.z), pack2(b1.w, b1.w) };
            #pragma unroll
            for (int mp = 0; mp < 4; mp++)
                #pragma unroll
                for (int n = 0; n < 8; n++)
                    acc[mp][n] = ffma2(ap[mp], bp[n], acc[mp][n]);
        }
        if (it < nk) {
            buf ^= 1;
            #pragma unroll
            for (int i = 0; i < 4; i++) {
                int lin = tid + i * 256;
                As[buf][lin & 7][lin >> 3] = sa[i];
                Bs[buf][lin >> 7][lin & 127] = sb[i];
            }
            __syncthreads();
        }
    }

    #pragma unroll
    for (int mp = 0; mp < 4; mp++) {
        int gr0 = rowBase + ty * 8 + 2 * mp;
        int gr1 = gr0 + 1;
        #pragma unroll
        for (int n = 0; n < 8; n++) {
            int gc = colBase + tx * 8 + n;
            if (gc >= N) continue;
            float2 v = unpack2(acc[mp][n]);
            float bv = bias ? bias[gc] : 0.f;
            if (gr0 < M) C[(size_t)gr0 * N + gc] = v.x + bv;
            if (gr1 < M) C[(size_t)gr1 * N + gc] = v.y + bv;
        }
    }
}

// ---------------- LayerNorm over DH=1024 ----------------
__global__ void __launch_bounds__(256) ln_kernel(
    const float* __restrict__ src,
    const float* __restrict__ gamma, const float* __restrict__ beta,
    int npb, int node_off, int residual)
{
    int r = blockIdx.x;
    int bb = r / npb, n = r % npb;
    size_t srow = (size_t)r * DH_;
    size_t drow = ((size_t)bb * NT_ + node_off + n) * DH_;
    int t = threadIdx.x;
    float v[4];
    #pragma unroll
    for (int i = 0; i < 4; i++) {
        int d = t + i * 256;
        float val = src[srow + d];
        if (residual) val += g_x[drow + d];
        v[i] = val;
    }
    float s  = v[0] + v[1] + v[2] + v[3];
    float sq = v[0]*v[0] + v[1]*v[1] + v[2]*v[2] + v[3]*v[3];
    __shared__ float shs[8], shq[8], fin[2];
    #pragma unroll
    for (int o = 16; o; o >>= 1) {
        s  += __shfl_xor_sync(0xffffffffu, s,  o);
        sq += __shfl_xor_sync(0xffffffffu, sq, o);
    }
    if ((t & 31) == 0) { shs[t >> 5] = s; shq[t >> 5] = sq; }
    __syncthreads();
    if (t == 0) {
        float a = 0.f, b2 = 0.f;
        #pragma unroll
        for (int i = 0; i < 8; i++) { a += shs[i]; b2 += shq[i]; }
        float mean = a * (1.f / DH_);
        float var  = b2 * (1.f / DH_) - mean * mean;
        fin[0] = mean;
        fin[1] = rsqrtf(var + 1e-5f);
    }
    __syncthreads();
    float mean = fin[0], inv = fin[1];
    #pragma unroll
    for (int i = 0; i < 4; i++) {
        int d = t + i * 256;
        g_x[drow + d] = (v[i] - mean) * inv * gamma[d] + beta[d];
    }
}

// ---------------- text masked mean-pool ----------------
__global__ void text_pool_kernel(const int* __restrict__ ids, const int* __restrict__ am,
                                 const float* __restrict__ temb)
{
    int b = blockIdx.y;
    int d = blockIdx.x * 256 + threadIdx.x;
    float sum = 0.f, cnt = 0.f;
    for (int l = 0; l < LQ; l++) {
        float mv = (float)am[b * LQ + l];
        sum += mv * temb[(size_t)ids[b * LQ + l] * DH_ + d];
        cnt += mv;
    }
    g_pool[b * DH_ + d] = sum / fmaxf(cnt, 1.f);
}

// ---------------- q projection: M=8 dedicated (one thread per output) ----------------
__global__ void qproj_kernel(const float* __restrict__ W, const float* __restrict__ bias)
{
    int b = blockIdx.y;
    int d = blockIdx.x * 256 + threadIdx.x;
    const float* pr = g_pool + b * DH_;
    float sv = 0.f;
    #pragma unroll 4
    for (int k = 0; k < DH_; k++) sv += pr[k] * W[(size_t)k * DH_ + d];
    g_y[(size_t)b * DH_ + d] = sv + bias[d];
}

// ---------------- add type embeddings ----------------
__global__ void type_add_kernel(const int* __restrict__ types, const float* __restrict__ temb)
{
    size_t idx = (size_t)blockIdx.x * 256 + threadIdx.x;
    int node = (int)(idx >> 10);
    int d = (int)(idx & (DH_ - 1));
    g_x[idx] += temb[types[node] * DH_ + d];
}

// ---------------- adjacency -> bitmask ----------------
__global__ void mask_kernel(const int* __restrict__ adj)
{
    int w = blockIdx.x * 256 + threadIdx.x;
    const int* row = adj + (size_t)w * 32;
    unsigned m = 0u;
    #pragma unroll
    for (int i = 0; i < 32; i++) m |= (row[i] > 0) ? (1u << i) : 0u;
    g_mb[w] = m;
}

// ---------------- per-node s,t and exp factors ----------------
__global__ void st_kernel(const float* __restrict__ asrc, const float* __restrict__ adst)
{
    int bn = blockIdx.x;
    int b = bn >> 10, n = bn & (NT_ - 1);
    int w = threadIdx.x >> 5, lane = threadIdx.x & 31;
    const float* hr = g_h + ((size_t)bn << 10) + (w << 7);
    float sv = 0.f, tv = 0.f;
    #pragma unroll
    for (int i = 0; i < 4; i++) {
        float hv = hr[lane + i * 32];
        sv += hv * asrc[w * DHD_ + lane + i * 32];
        tv += hv * adst[w * DHD_ + lane + i * 32];
    }
    #pragma unroll
    for (int o = 16; o; o >>= 1) {
        sv += __shfl_xor_sync(0xffffffffu, sv, o);
        tv += __shfl_xor_sync(0xffffffffu, tv, o);
    }
    if (lane == 0) {
        g_s[bn * NH_ + w] = sv;
        int idxT = ((b * NH_ + w) << 10) + n;
        g_tT [idxT] = tv;
        g_e1T[idxT] = expf(tv);
        g_e2T[idxT] = expf(0.2f * tv);
    }
}

// ---------------- softmax row stats ----------------
__global__ void stats_kernel()
{
    int bi = blockIdx.x;
    int b = bi >> 10;
    int hd = threadIdx.x >> 5, lane = threadIdx.x & 31;
    float si = g_s[bi * NH_ + hd];
    const unsigned* mrow = g_mb + (size_t)bi * 32;
    const float* tT  = g_tT  + ((b * NH_ + hd) << 10);
    const float* e1T = g_e1T + ((b * NH_ + hd) << 10);
    const float* e2T = g_e2T + ((b * NH_ + hd) << 10);
    float S1 = 0.f, S2 = 0.f;
    for (int it = 0; it < 32; it++) {
        unsigned wd = mrow[it];
        if ((wd >> lane) & 1u) {
            int j = it * 32 + lane;
            if (si + tT[j] >= 0.f) S1 += e1T[j]; else S2 += e2T[j];
        }
    }
    #pragma unroll
    for (int o = 16; o; o >>= 1) {
        S1 += __shfl_xor_sync(0xffffffffu, S1, o);
        S2 += __shfl_xor_sync(0xffffffffu, S2, o);
    }
    if (lane == 0) {
        float e1 = expf(si), e2 = expf(0.2f * si);
        float inv = 1.f / (e1 * S1 + e2 * S2);
        g_p1[bi * NH_ + hd] = e1 * inv;
        g_p2[bi * NH_ + hd] = e2 * inv;
    }
}

// ---------------- GAT aggregation: generated-A GEMM, double-buffered, FFMA2 ----------------
// BM=64, BN=128, BK=32, 256 threads.
__global__ void __launch_bounds__(256) gat_agg_kernel()
{
    int b = blockIdx.z, hd = blockIdx.y;
    int rowBase = blockIdx.x * 64;
    int tid = threadIdx.x;
    int tx = tid & 15, ty = tid >> 4;

    __shared__ __align__(16) float  As[2][32][64];   // [k(j)][m(i)]
    __shared__ __align__(16) float4 Bs[2][32][32];   // [k(j)][d/4]

    int m  = tid & 63;
    int jb = tid >> 6;
    int bi_m = (b << 10) + rowBase + m;
    float smv = g_s [bi_m * NH_ + hd];
    float pr1 = g_p1[bi_m * NH_ + hd];
    float pr2 = g_p2[bi_m * NH_ + hd];
    const unsigned* mrow = g_mb + (size_t)bi_m * 32;
    const float* tT  = g_tT  + ((b * NH_ + hd) << 10);
    const float* e1T = g_e1T + ((b * NH_ + hd) << 10);
    const float* e2T = g_e2T + ((b * NH_ + hd) << 10);

    // acc[a][np]: row (ty*4+a), col pair (tx*8+2np, +1)
    u64 acc[4][4];
    #pragma unroll
    for (int a = 0; a < 4; a++)
        #pragma unroll
        for (int n = 0; n < 4; n++) acc[a][n] = pack2(0.f, 0.f);

    float4 pb[4];
    float  wv[8];

    // prefetch tile 0
    #pragma unroll
    for (int i = 0; i < 4; i++) {
        int lin = tid + i * 256;
        int r = lin >> 5, c4 = lin & 31;
        const float4* src = (const float4*)(g_h + (((size_t)((b << 10) + r)) << 10) + (hd << 7));
        pb[i] = src[c4];
    }
    {
        unsigned mword = mrow[0];
        #pragma unroll
        for (int i = 0; i < 8; i++) {
            int jj = jb + i * 4;
            float w = 0.f;
            if ((mword >> jj) & 1u)
                w = (smv + tT[jj] >= 0.f) ? pr1 * e1T[jj] : pr2 * e2T[jj];
            wv[i] = w;
        }
    }
    #pragma unroll
    for (int i = 0; i < 4; i++) {
        int lin = tid + i * 256;
        Bs[0][lin >> 5][lin & 31] = pb[i];
    }
    #pragma unroll
    for (int i = 0; i < 8; i++) As[0][jb + i * 4][m] = wv[i];
    __syncthreads();

    int buf = 0;
    for (int it = 1; it <= 32; it++) {
        if (it < 32) {
            int k0 = it << 5;
            #pragma unroll
            for (int i = 0; i < 4; i++) {
                int lin = tid + i * 256;
                int r = lin >> 5, c4 = lin & 31;
                const float4* src = (const float4*)(g_h + (((size_t)((b << 10) + k0 + r)) << 10) + (hd << 7));
                pb[i] = src[c4];
            }
            unsigned mword = mrow[it];
            #pragma unroll
            for (int i = 0; i < 8; i++) {
                int jj = jb + i * 4;
                float w = 0.f;
                if ((mword >> jj) & 1u) {
                    int j = k0 + jj;
                    w = (smv + tT[j] >= 0.f) ? pr1 * e1T[j] : pr2 * e2T[j];
                }
                wv[i] = w;
            }
        }
        // compute current buffer
        #pragma unroll
        for (int k = 0; k < 32; k++) {
            float4 ra = *(const float4*)&As[buf][k][ty << 2];
            u64 ap[4] = { pack2(ra.x, ra.x), pack2(ra.y, ra.y),
                          pack2(ra.z, ra.z), pack2(ra.w, ra.w) };
            const u64* brow = (const u64*)&Bs[buf][k][0];
            u64 bp[4];
            #pragma unroll
            for (int n = 0; n < 4; n++) bp[n] = brow[tx * 4 + n];
            #pragma unroll
            for (int a = 0; a < 4; a++)
                #pragma unroll
                for (int n = 0; n < 4; n++)
                    acc[a][n] = ffma2(ap[a], bp[n], acc[a][n]);
        }
        if (it < 32) {
            buf ^= 1;
            #pragma unroll
            for (int i = 0; i < 4; i++) {
                int lin = tid + i * 256;
                Bs[buf][lin >> 5][lin & 31] = pb[i];
            }
            #pragma unroll
            for (int i = 0; i < 8; i++) As[buf][jb + i * 4][m] = wv[i];
            __syncthreads();
        }
    }

    #pragma unroll
    for (int a = 0; a < 4; a++) {
        int gi = rowBase + (ty << 2) + a;
        float* dst = g_y + (((size_t)((b << 10) + gi)) << 10) + (hd << 7) + (tx << 3);
        float2 v0 = unpack2(acc[a][0]);
        float2 v1 = unpack2(acc[a][1]);
        float2 v2 = unpack2(acc[a][2]);
        float2 v3 = unpack2(acc[a][3]);
        float4* d4 = (float4*)dst;
        d4[0] = make_float4(v0.x, v0.y, v1.x, v1.y);
        d4[1] = make_float4(v2.x, v2.y, v3.x, v3.y);
    }
}

// ---------------- readout score per node ----------------
__global__ void score_kernel(const float* __restrict__ rw, const float* __restrict__ rb)
{
    int gwarp = (blockIdx.x * 256 + threadIdx.x) >> 5;
    int lane = threadIdx.x & 31;
    const float* xr = g_x + ((size_t)gwarp << 10);
    float sv = 0.f;
    #pragma unroll
    for (int i = 0; i < 32; i++) sv += xr[lane + i * 32] * rw[lane + i * 32];
    #pragma unroll
    for (int o = 16; o; o >>= 1) sv += __shfl_xor_sync(0xffffffffu, sv, o);
    if (lane == 0) g_sc[gwarp] = sv + rb[0];
}

// ---------------- softmax over nodes + weighted pool ----------------
__global__ void readout_pool_kernel()
{
    int b = blockIdx.y;
    int d = blockIdx.x * 256 + threadIdx.x;
    int tid = threadIdx.x;
    __shared__ float p[NT_];
    __shared__ float red[9];
    float mx = -1e30f;
    #pragma unroll
    for (int i = 0; i < 4; i++) mx = fmaxf(mx, g_sc[b * NT_ + tid + i * 256]);
    #pragma unroll
    for (int o = 16; o; o >>= 1) mx = fmaxf(mx, __shfl_xor_sync(0xffffffffu, mx, o));
    if ((tid & 31) == 0) red[tid >> 5] = mx;
    __syncthreads();
    if (tid == 0) {
        float mm = red[0];
        #pragma unroll
        for (int i = 1; i < 8; i++) mm = fmaxf(mm, red[i]);
        red[8] = mm;
    }
    __syncthreads();
    mx = red[8];
    float sum = 0.f;
    #pragma unroll
    for (int i = 0; i < 4; i++) {
        int n = tid + i * 256;
        float e = expf(g_sc[b * NT_ + n] - mx);
        p[n] = e; sum += e;
    }
    #pragma unroll
    for (int o = 16; o; o >>= 1) sum += __shfl_xor_sync(0xffffffffu, sum, o);
    __syncthreads();
    if ((tid & 31) == 0) red[tid >> 5] = sum;
    __syncthreads();
    if (tid == 0) {
        float ss2 = 0.f;
        #pragma unroll
        for (int i = 0; i < 8; i++) ss2 += red[i];
        red[8] = 1.f / ss2;
    }
    __syncthreads();
    float inv = red[8];
    float acc = 0.f;
    for (int n = 0; n < NT_; n++)
        acc += p[n] * g_x[(((size_t)(b << 10)) + n) * DH_ + d];
    g_gv[b * DH_ + d] = acc * inv;
}

// ---------------- candidate scorer ----------------
__global__ void cs1_kernel(const float* __restrict__ W1, const float* __restrict__ b1)
{
    int b = blockIdx.y;
    int d = blockIdx.x * 256 + threadIdx.x;
    const float* gr = g_gv + b * DH_;
    float sv = 0.f;
    #pragma unroll 4
    for (int k = 0; k < DH_; k++) sv += gr[k] * W1[(size_t)k * DH_ + d];
    sv += b1[d];
    float u = 0.7978845608028654f * (sv + 0.044715f * sv * sv * sv);
    g_hm[b * DH_ + d] = 0.5f * sv * (1.f + tanhf(u));
}

__global__ void cs2_kernel(const float* __restrict__ W2, const float* __restrict__ b2,
                           float* __restrict__ out)
{
    int b = blockIdx.x;
    int tid = threadIdx.x;
    float sv = 0.f;
    for (int i = tid; i < DH_; i += 256) sv += g_hm[b * DH_ + i] * W2[i];
    #pragma unroll
    for (int o = 16; o; o >>= 1) sv += __shfl_xor_sync(0xffffffffu, sv, o);
    __shared__ float red[8];
    if ((tid & 31) == 0) red[tid >> 5] = sv;
    __syncthreads();
    if (tid == 0) {
        float tot = 0.f;
        #pragma unroll
        for (int i = 0; i < 8; i++) tot += red[i];
        out[b] = tot + b2[0];
    }
}

extern "C" void kernel_launch(void* const* d_in, const int* in_sizes, int n_in,
                              void* d_out, int out_size)
{
    const float* visf   = (const float*)d_in[0];
    const int*   qids   = (const int*)  d_in[1];
    const int*   qam    = (const int*)  d_in[2];
    const float* kgf    = (const float*)d_in[3];
    const int*   adj    = (const int*)  d_in[4];
    const int*   types  = (const int*)  d_in[5];
    const float* vis_W  = (const float*)d_in[6];
    const float* vis_b  = (const float*)d_in[7];
    const float* vis_lg = (const float*)d_in[8];
    const float* vis_lb = (const float*)d_in[9];
    const float* tok    = (const float*)d_in[10];
    const float* q_W    = (const float*)d_in[11];
    const float* q_b    = (const float*)d_in[12];
    const float* q_lg   = (const float*)d_in[13];
    const float* q_lb   = (const float*)d_in[14];
    const float* kg_W   = (const float*)d_in[15];
    const float* kg_b   = (const float*)d_in[16];
    const float* kg_lg  = (const float*)d_in[17];
    const float* kg_lb  = (const float*)d_in[18];
    const float* temb   = (const float*)d_in[19];
    const float* gat_W  = (const float*)d_in[20];
    const float* gat_b  = (const float*)d_in[21];
    const float* a_src  = (const float*)d_in[22];
    const float* a_dst  = (const float*)d_in[23];
    const float* gat_lg = (const float*)d_in[24];
    const float* gat_lb = (const float*)d_in[25];
    const float* rW     = (const float*)d_in[26];
    const float* rb     = (const float*)d_in[27];
    const float* csW1   = (const float*)d_in[28];
    const float* csb1   = (const float*)d_in[29];
    const float* csW2   = (const float*)d_in[30];
    const float* csb2   = (const float*)d_in[31];
    float* out = (float*)d_out;

    float *x, *h, *y;
    cudaGetSymbolAddress((void**)&x, g_x);
    cudaGetSymbolAddress((void**)&h, g_h);
    cudaGetSymbolAddress((void**)&y, g_y);

    // 1. visual projection + LN  -> x[:, 0:100]
    sgemm_kernel<<<dim3(8, (NB*NV_ + 127) / 128), 256>>>(visf, vis_W, vis_b, y, NB*NV_, DH_, DV_);
    ln_kernel<<<NB*NV_, 256>>>(y, vis_lg, vis_lb, NV_, 0, 0);

    // 2. text pool + proj + LN   -> x[:, 100]
    text_pool_kernel<<<dim3(4, NB), 256>>>(qids, qam, tok);
    qproj_kernel<<<dim3(4, NB), 256>>>(q_W, q_b);
    ln_kernel<<<NB, 256>>>(y, q_lg, q_lb, 1, NV_, 0);

    // 3. KG projection + LN      -> x[:, 101:1024]
    sgemm_kernel<<<dim3(8, (NB*NKG_ + 127) / 128), 256>>>(kgf, kg_W, kg_b, y, NB*NKG_, DH_, DK_);
    ln_kernel<<<NB*NKG_, 256>>>(y, kg_lg, kg_lb, NKG_, NV_ + 1, 0);

    // 4. type embeddings, adjacency bitmask
    type_add_kernel<<<(NB*NT_*DH_) / 256, 256>>>(types, temb);
    mask_kernel<<<(NB*NT_*32) / 256, 256>>>(adj);

    // 5. GAT layers
    for (int l = 0; l < NL_; l++) {
        sgemm_kernel<<<dim3(8, 64), 256>>>(x, gat_W + (size_t)l*DH_*DH_, gat_b + l*DH_, h,
                                           NB*NT_, DH_, DH_);
        st_kernel<<<NB*NT_, 256>>>(a_src + l*NH_*DHD_, a_dst + l*NH_*DHD_);
        stats_kernel<<<NB*NT_, 256>>>();
        gat_agg_kernel<<<dim3(16, NH_, NB), 256>>>();
        ln_kernel<<<NB*NT_, 256>>>(y, gat_lg + l*DH_, gat_lb + l*DH_, NT_, 0, 1);
    }

    // 6. readout + scorer
    score_kernel<<<(NB*NT_*32) / 256, 256>>>(rW, rb);
    readout_pool_kernel<<<dim3(4, NB), 256>>>();
    cs1_kernel<<<dim3(4, NB), 256>>>(csW1, csb1);
    cs2_kernel<<<NB, 256>>>(csW2, csb2, out);
}